// round 11
// baseline (speedup 1.0000x reference)
#include <cuda_runtime.h>

// Graph TopK pooling — R10: ONE persistent kernel, grid-wide barriers.
// Phases: A scores+hist0 | B redundant select0, hist1 | C redundant select1,
// node-tile counts (+zero hist1) | D redundant scan + node write (+zero hist2)
// | E edge tiles (lookback) + x-gather (atomic chunks) + attr copy.
// Residency: grid=592, __launch_bounds__(256,4), smem ~15.5KB -> all blocks
// resident on 148+ SMs; grid barriers are deadlock-free.
// Cross-replay scratch invariant: globals zero at load; phase A zeroes etile/xctr
// (consumed in prior replay E), C zeroes hist1/c1, D zeroes hist2/c2.

#define NMAX 100352
#define GRID 592
#define TPB  256

__device__ float        g_scores[NMAX];
__device__ unsigned int g_hist1[65536];
__device__ unsigned int g_hist2[65536];
__device__ unsigned int g_c1[256];
__device__ unsigned int g_c2[256];
__device__ int          g_map[NMAX];
__device__ int          g_poolidx[NMAX / 2 + 256];
__device__ int          g_tcnt[128];
__device__ unsigned int g_etile[512];
__device__ unsigned int g_xctr;
__device__ unsigned int g_bar_cnt;
__device__ unsigned int g_bar_gen;

// ---------------- grid-wide sense-reversing barrier ----------------
__device__ __forceinline__ void grid_bar() {
    __syncthreads();
    if (threadIdx.x == 0) {
        unsigned int gen = atomicAdd(&g_bar_gen, 0u);
        __threadfence();
        if (atomicAdd(&g_bar_cnt, 1u) == gridDim.x - 1u) {
            g_bar_cnt = 0u;
            __threadfence();
            atomicAdd(&g_bar_gen, 1u);
        } else {
            while (atomicAdd(&g_bar_gen, 0u) == gen) __nanosleep(64);
        }
        __threadfence();
    }
    __syncthreads();
}

// ---------------- redundant per-block radix select (reads ~1.3KB from L2) ----------------
__device__ __forceinline__ void block_select(
    const unsigned int* __restrict__ C, const unsigned int* __restrict__ H,
    int k, int* sc, int* sf2, int* s_bin, int* s_rem)
{
    int t = threadIdx.x;
    int v = (int)C[t];
    sc[t] = v;
    __syncthreads();
    for (int off = 1; off < 256; off <<= 1) {
        int u = (t >= off) ? sc[t - off] : 0;
        __syncthreads();
        sc[t] += u;
        __syncthreads();
    }
    int excl = sc[t] - v;
    if (k >= excl && k < excl + v) { *s_bin = t; *s_rem = k - excl; }
    __syncthreads();
    int wb = *s_bin;
    int rem0 = *s_rem;
    __syncthreads();
    uint4 q = make_uint4(0, 0, 0, 0);
    int fv = 0;
    if (t < 64) {
        q = ((const uint4*)H)[wb * 64 + t];
        fv = (int)(q.x + q.y + q.z + q.w);
        sf2[t] = fv;
    }
    __syncthreads();
    for (int off = 1; off < 64; off <<= 1) {
        int u = (t >= off && t < 64) ? sf2[t - off] : 0;
        __syncthreads();
        if (t < 64) sf2[t] += u;
        __syncthreads();
    }
    if (t < 64) {
        int e2 = sf2[t] - fv;
        if (rem0 >= e2 && rem0 < e2 + fv) {
            int r = rem0 - e2;
            int bin;
            if (r < (int)q.x)                       { bin = wb * 256 + t * 4 + 0; }
            else { r -= (int)q.x; if (r < (int)q.y) { bin = wb * 256 + t * 4 + 1; }
            else { r -= (int)q.y; if (r < (int)q.z) { bin = wb * 256 + t * 4 + 2; }
            else { r -= (int)q.z;                     bin = wb * 256 + t * 4 + 3; } } }
            *s_bin = bin; *s_rem = r;
        }
    }
    __syncthreads();
}

// ---------------- warp-parallel decoupled lookback (warp 0) ----------------
__device__ __forceinline__ int lookback_excl(unsigned int* tiles, int tile, int cnt, int t) {
    if (t == 0) {
        unsigned int word = (((tile == 0) ? 2u : 1u) << 30) | (unsigned)cnt;
        atomicExch(&tiles[tile], word);
    }
    __syncwarp();
    int excl = 0;
    if (tile > 0) {
        int p = tile - 1;
        bool done = false;
        while (!done) {
            int idx = p - t;
            unsigned int v = 0;
            if (idx >= 0) {
                v = *((volatile unsigned int*)&tiles[idx]);
                while ((v >> 30) == 0u) {
                    __nanosleep(40);
                    v = *((volatile unsigned int*)&tiles[idx]);
                }
            }
            unsigned int fl = (idx >= 0) ? (v >> 30) : 0u;
            unsigned int pm = __ballot_sync(0xffffffffu, fl == 2u);
            int stop_lane = (pm != 0u) ? (__ffs(pm) - 1) : 32;
            int val = (idx >= 0 && t <= stop_lane) ? (int)(v & 0x3fffffffu) : 0;
#pragma unroll
            for (int o = 16; o > 0; o >>= 1) val += __shfl_down_sync(0xffffffffu, val, o);
            if (t == 0) excl += val;
            done = (pm != 0u) || (p - 31 < 0);
            p -= 32;
        }
        if (t == 0) atomicExch(&tiles[tile], (2u << 30) | (unsigned)(excl + cnt));
    }
    return excl;  // lane 0
}

__global__ void __launch_bounds__(TPB, 4)
k_all(const float* __restrict__ x, const float* __restrict__ ea,
      const float* __restrict__ w, const float* __restrict__ b,
      const int* __restrict__ ei, int N, int E, int NK, int Ek,
      float* __restrict__ out_x, float* __restrict__ out_ei,
      float* __restrict__ out_eo, float* __restrict__ out_ea,
      float* __restrict__ out_pi, float* __restrict__ out_pe)
{
    __shared__ int sc[256];
    __shared__ int sf2[64];
    __shared__ int s_bin, s_rem;
    __shared__ unsigned char sf[4096];
    __shared__ int ssum[256];
    __shared__ short s_list[4096];
    __shared__ int s_scan[128];
    __shared__ int s_gb;
    __shared__ int s_chunk;

    int bid = blockIdx.x, t = threadIdx.x;
    int G = gridDim.x;
    int lane = t & 31;

    // ================= Phase A: zero replay scratch + scores + hist0 =================
    if (bid == 0) {
        if (t == 0) g_xctr = 0u;
        g_etile[t] = 0u; g_etile[256 + t] = 0u;
    }
    {
        int gw = bid * (TPB / 32) + (t >> 5);
        int TW = G * (TPB / 32);
        for (int node = gw; node < N; node += TW) {
            float4 xv = ((const float4*)x)[node * 32 + lane];
            float4 wv = ((const float4*)w)[lane];
            float s = xv.x * wv.x + xv.y * wv.y + xv.z * wv.z + xv.w * wv.w;
#pragma unroll
            for (int o = 16; o > 0; o >>= 1) s += __shfl_down_sync(0xffffffffu, s, o);
            if (lane == 0) {
                float z = s + b[0];
                float scv;
                if (z >= 0.f) scv = 1.f / (1.f + expf(-z));
                else { float e = expf(z); scv = e / (1.f + e); }
                g_scores[node] = scv;
                unsigned int bits = __float_as_uint(scv);  // scv>0: uint order == float order
                atomicAdd(&g_hist1[bits >> 16], 1u);
                atomicAdd(&g_c1[bits >> 24], 1u);
            }
        }
    }
    grid_bar();  // ---- BAR1: hist0 complete ----

    // ================= Phase B: redundant select0; then hist1 of matches =================
    block_select(g_c1, g_hist1, NK - 1, sc, sf2, &s_bin, &s_rem);
    int prefix = s_bin;
    int krem   = s_rem;
    for (int idx = bid * TPB + t; idx < N; idx += G * TPB) {
        unsigned int bits = __float_as_uint(g_scores[idx]);
        if ((int)(bits >> 16) == prefix) {
            atomicAdd(&g_hist2[bits & 0xffffu], 1u);
            atomicAdd(&g_c2[(bits >> 8) & 0xffu], 1u);
        }
    }
    grid_bar();  // ---- BAR2: hist1 complete ----

    // ================= Phase C: redundant select1 -> tbits; node tile counts; zero hist1 =================
    block_select(g_c2, g_hist2, krem, sc, sf2, &s_bin, &s_rem);
    unsigned int tb = ((unsigned)prefix << 16) | (unsigned)s_bin;
    int nbn = (N + 1023) >> 10;
    for (int tile = bid; tile < nbn; tile += G) {
        int base = tile * 1024;
        int c = 0;
        for (int i = t; i < 1024; i += TPB) {
            int n = base + i;
            if (n < N) c += (__float_as_uint(g_scores[n]) >= tb) ? 1 : 0;
        }
        ssum[t] = c;
        __syncthreads();
        for (int off = 128; off > 0; off >>= 1) {
            if (t < off) ssum[t] += ssum[t + off];
            __syncthreads();
        }
        if (t == 0) g_tcnt[tile] = ssum[0];
        __syncthreads();
    }
    if (bid >= nbn) {  // idle blocks zero hist1/c1 for next replay
        int zb = bid - nbn, ZG = G - nbn;
        for (int i = zb * TPB + t; i < 65536; i += ZG * TPB) g_hist1[i] = 0u;
        if (zb == 0) g_c1[t] = 0u;
    }
    grid_bar();  // ---- BAR3: tile counts complete ----

    // ================= Phase D: redundant tcnt scan; node write; zero hist2 =================
    if (t < 128) s_scan[t] = (t < nbn) ? g_tcnt[t] : 0;
    __syncthreads();
    for (int off = 1; off < 128; off <<= 1) {
        int u = (t >= off && t < 128) ? s_scan[t - off] : 0;
        __syncthreads();
        if (t < 128) s_scan[t] += u;
        __syncthreads();
    }
    for (int tile = bid; tile < nbn; tile += G) {
        int gb = (tile > 0) ? s_scan[tile - 1] : 0;
        int base = tile * 1024;
        for (int i = t; i < 1024; i += TPB) {
            int n = base + i;
            sf[i] = (n < N) ? (unsigned char)(__float_as_uint(g_scores[n]) >= tb) : (unsigned char)0;
        }
        __syncthreads();
        int loc[4];
        int s = 0;
#pragma unroll
        for (int j = 0; j < 4; j++) { loc[j] = s; s += sf[t * 4 + j]; }
        ssum[t] = s;
        __syncthreads();
        for (int off = 1; off < 256; off <<= 1) {
            int u = (t >= off) ? ssum[t - off] : 0;
            __syncthreads();
            ssum[t] += u;
            __syncthreads();
        }
        int texcl = ssum[t] - s;
#pragma unroll
        for (int j = 0; j < 4; j++) {
            int n = base + t * 4 + j;
            if (n >= N) continue;
            int m = -1;
            if (sf[t * 4 + j]) {
                int r = gb + texcl + loc[j];
                if (r < NK) {  // stable truncation: first NK masked nodes by index
                    m = r;
                    g_poolidx[r] = n;
                    out_pi[r] = (float)n;
                }
            }
            g_map[n] = m;
        }
        __syncthreads();
    }
    if (bid >= nbn) {  // idle blocks zero hist2/c2 for next replay
        int zb = bid - nbn, ZG = G - nbn;
        for (int i = zb * TPB + t; i < 65536; i += ZG * TPB) g_hist2[i] = 0u;
        if (zb == 0) g_c2[t] = 0u;
    }
    grid_bar();  // ---- BAR4: g_map complete ----

    // ================= Phase E: edge tiles (lookback) + attr copy, then x-gather =================
    int nbe = (E + 4095) >> 12;
    for (int tile = bid; tile < nbe; tile += G) {
        int base = tile * 4096;
        for (int i = t; i < 4096; i += TPB) {
            int e = base + i;
            unsigned char f = 0;
            if (e < E) {
                int sN = ei[e], dN = ei[E + e];
                f = (unsigned char)((g_map[sN] >= 0 && g_map[dN] >= 0) ? 1 : 0);
                out_pe[e] = f ? 1.0f : 0.0f;
            }
            sf[i] = f;
        }
        __syncthreads();
        int loc[16];
        int s = 0;
#pragma unroll
        for (int j = 0; j < 16; j++) { loc[j] = s; s += sf[t * 16 + j]; }
        ssum[t] = s;
        __syncthreads();
        for (int off = 1; off < 256; off <<= 1) {
            int u = (t >= off) ? ssum[t - off] : 0;
            __syncthreads();
            ssum[t] += u;
            __syncthreads();
        }
        int cnt = ssum[255];
        if (t < 32) {
            int excl = lookback_excl(g_etile, tile, cnt, t);
            if (t == 0) s_gb = excl;
        }
        __syncthreads();
        int texcl = ssum[t] - s;
        int gb = s_gb;
        for (int j = 0; j < 16; j++) {
            int i = t * 16 + j;
            int e = base + i;
            if (e < E && sf[i]) {
                int lr = texcl + loc[j];
                int r = gb + lr;
                s_list[lr] = (short)i;
                int sN = ei[e], dN = ei[E + e];   // L2 hit (tile just streamed)
                out_ei[r]      = (float)sN;
                out_ei[Ek + r] = (float)dN;
                out_eo[r]      = (float)g_map[sN];
                out_eo[Ek + r] = (float)g_map[dN];
            }
        }
        __syncthreads();
        // attr copy: warp per kept row, 128B coalesced
        int wid = t >> 5;
        for (int j = wid; j < cnt; j += (TPB / 32)) {
            size_t e = (size_t)(base + (int)s_list[j]);
            size_t r = (size_t)(gb + j);
            out_ea[r * 32 + lane] = ea[e * 32 + lane];
        }
        __syncthreads();
    }

    // x-gather: atomic chunk queue, all blocks drain as they finish edge work
    int totchunks = (NK * 32 + TPB - 1) / TPB;
    for (;;) {
        if (t == 0) s_chunk = (int)atomicAdd(&g_xctr, 1u);
        __syncthreads();
        int c = s_chunk;
        __syncthreads();
        if (c >= totchunks) break;
        int tid = c * TPB + t;
        if (tid < NK * 32) {
            int r = tid >> 5, col = tid & 31;
            int n = g_poolidx[r];
            ((float4*)out_x)[tid] = ((const float4*)x)[n * 32 + col];
        }
    }
}

extern "C" void kernel_launch(void* const* d_in, const int* in_sizes, int n_in,
                              void* d_out, int out_size) {
    const float* x  = (const float*)d_in[0];   // (1, N, 128)
    const float* ea = (const float*)d_in[1];   // (1, E, 32)
    const float* w  = (const float*)d_in[2];   // (1, 128)
    const float* b  = (const float*)d_in[3];   // (1,)
    const int*   ei = (const int*)d_in[4];     // (2, E)

    int N  = in_sizes[0] / 128;
    int E  = in_sizes[4] / 2;
    int NK = N / 2;
    long long Ek_ll = ((long long)out_size - (long long)NK * 129 - (long long)E) / 36;
    int Ek = (int)Ek_ll;

    float* out    = (float*)d_out;
    float* out_x  = out;
    float* out_ei = out_x + (size_t)NK * 128;
    float* out_eo = out_ei + 2 * (size_t)Ek;
    float* out_ea = out_eo + 2 * (size_t)Ek;
    float* out_pi = out_ea + 32 * (size_t)Ek;
    float* out_pe = out_pi + (size_t)NK;

    k_all<<<GRID, TPB>>>(x, ea, w, b, ei, N, E, NK, Ek,
                         out_x, out_ei, out_eo, out_ea, out_pi, out_pe);
}

// round 13
// speedup vs baseline: 1.1033x; 1.1033x over previous
#include <cuda_runtime.h>

// Graph TopK pooling — R11: 5 launches, R5 skeleton + redundant in-kernel selects.
//  L1 k_scores : scores + hi16/hi8 histogram + zero tile-states (ntile/etile)
//  L2 k_phase1 : per-block redundant select0 -> prefix; lo16 histogram; block0
//                publishes g_prefix/g_krem
//  L3 k_nodes  : per-block redundant select1 -> tbits; lookback node compaction
//                -> g_map/g_poolidx/out_pi; zeroes hist1/c1
//  L4 k_edges  : staged edge tiles: flags+pe, scan, lookback, compact ->
//                out_ei/out_eo + g_kept; zeroes hist2/c2
//  L5 k_gather : pure gathers: edge_attr rows (g_kept) + new_x rows (g_poolidx)
// Cross-replay invariant: globals zero at load; hist1/c1 zeroed in L3 (last read
// in L2), hist2/c2 in L4 (last read in L3), tile states in L1 (last read L3/L4
// of previous replay). All races are none or identical-value.

#define NMAX 100352
#define EMAX 1600000

__device__ float        g_scores[NMAX];
__device__ unsigned int g_hist1[65536];
__device__ unsigned int g_hist2[65536];
__device__ unsigned int g_c1[256];
__device__ unsigned int g_c2[256];
__device__ int          g_prefix;
__device__ int          g_krem;
__device__ int          g_map[NMAX];
__device__ int          g_poolidx[NMAX / 2 + 256];
__device__ int          g_kept[EMAX];
__device__ unsigned int g_ntile[256];   // packed flag<<30 | value
__device__ unsigned int g_etile[512];

// ---------------- redundant per-block radix select (~1.3 KB of L2 reads) ----------------
__device__ __forceinline__ void block_select(
    const unsigned int* __restrict__ C, const unsigned int* __restrict__ H,
    int k, int* sc, int* sf2, int* s_bin, int* s_rem)
{
    int t = threadIdx.x;
    int v = (int)C[t];
    sc[t] = v;
    __syncthreads();
    for (int off = 1; off < 256; off <<= 1) {
        int u = (t >= off) ? sc[t - off] : 0;
        __syncthreads();
        sc[t] += u;
        __syncthreads();
    }
    int excl = sc[t] - v;
    if (k >= excl && k < excl + v) { *s_bin = t; *s_rem = k - excl; }
    __syncthreads();
    int wb = *s_bin;
    int rem0 = *s_rem;
    __syncthreads();
    uint4 q = make_uint4(0, 0, 0, 0);
    int fv = 0;
    if (t < 64) {
        q = ((const uint4*)H)[wb * 64 + t];
        fv = (int)(q.x + q.y + q.z + q.w);
        sf2[t] = fv;
    }
    __syncthreads();
    for (int off = 1; off < 64; off <<= 1) {
        int u = (t >= off && t < 64) ? sf2[t - off] : 0;
        __syncthreads();
        if (t < 64) sf2[t] += u;
        __syncthreads();
    }
    if (t < 64) {
        int e2 = sf2[t] - fv;
        if (rem0 >= e2 && rem0 < e2 + fv) {
            int r = rem0 - e2;
            int bin;
            if (r < (int)q.x)                       { bin = wb * 256 + t * 4 + 0; }
            else { r -= (int)q.x; if (r < (int)q.y) { bin = wb * 256 + t * 4 + 1; }
            else { r -= (int)q.y; if (r < (int)q.z) { bin = wb * 256 + t * 4 + 2; }
            else { r -= (int)q.z;                     bin = wb * 256 + t * 4 + 3; } } }
            *s_bin = bin; *s_rem = r;
        }
    }
    __syncthreads();
}

// ---------------- L1: scores (warp/node) + phase-0 histogram + tile zeroing ----------------
__global__ void k_scores(const float* __restrict__ x, const float* __restrict__ w,
                         const float* __restrict__ b, int N) {
    int bidx = blockIdx.x, t = threadIdx.x;
    if (bidx == 0) {            // zero tile states consumed later this replay
        g_ntile[t] = 0u;
        g_etile[t] = 0u; g_etile[256 + t] = 0u;
    }
    int gtid = bidx * blockDim.x + t;
    int node = gtid >> 5, lane = gtid & 31;
    if (node >= N) return;
    float4 xv = ((const float4*)x)[node * 32 + lane];
    float4 wv = ((const float4*)w)[lane];
    float s = xv.x * wv.x + xv.y * wv.y + xv.z * wv.z + xv.w * wv.w;
#pragma unroll
    for (int o = 16; o > 0; o >>= 1) s += __shfl_down_sync(0xffffffffu, s, o);
    if (lane == 0) {
        float z = s + b[0];
        float sc;
        if (z >= 0.f) sc = 1.f / (1.f + expf(-z));
        else { float e = expf(z); sc = e / (1.f + e); }
        g_scores[node] = sc;
        unsigned int bits = __float_as_uint(sc);  // sc > 0: uint order == float order
        atomicAdd(&g_hist1[bits >> 16], 1u);      // hist1/c1 zeroed by prior replay L3
        atomicAdd(&g_c1[bits >> 24], 1u);
    }
}

// ---------------- L2: redundant select0 + phase-1 histogram ----------------
__global__ void k_phase1(int N, int NK) {
    __shared__ int sc[256];
    __shared__ int sf2[64];
    __shared__ int s_bin, s_rem;
    int t = threadIdx.x;
    block_select(g_c1, g_hist1, NK - 1, sc, sf2, &s_bin, &s_rem);
    int prefix = s_bin;
    if (blockIdx.x == 0 && t == 0) { g_prefix = prefix; g_krem = s_rem; }
    int idx = blockIdx.x * blockDim.x + t;
    if (idx >= N) return;
    unsigned int bits = __float_as_uint(g_scores[idx]);
    if ((int)(bits >> 16) == prefix) {
        atomicAdd(&g_hist2[bits & 0xffffu], 1u);  // hist2/c2 zeroed by prior replay L4
        atomicAdd(&g_c2[(bits >> 8) & 0xffu], 1u);
    }
}

// ---------------- warp-parallel decoupled lookback (warp 0) ----------------
__device__ __forceinline__ int lookback_excl(unsigned int* tiles, int tile, int cnt, int t) {
    if (t == 0) {
        unsigned int word = (((tile == 0) ? 2u : 1u) << 30) | (unsigned)cnt;
        atomicExch(&tiles[tile], word);
    }
    __syncwarp();
    int excl = 0;
    if (tile > 0) {
        int p = tile - 1;
        bool done = false;
        while (!done) {
            int idx = p - t;
            unsigned int v = 0;
            if (idx >= 0) {
                v = *((volatile unsigned int*)&tiles[idx]);
                while ((v >> 30) == 0u) {
                    __nanosleep(40);
                    v = *((volatile unsigned int*)&tiles[idx]);
                }
            }
            unsigned int fl = (idx >= 0) ? (v >> 30) : 0u;
            unsigned int pm = __ballot_sync(0xffffffffu, fl == 2u);
            int stop_lane = (pm != 0u) ? (__ffs(pm) - 1) : 32;
            int val = (idx >= 0 && t <= stop_lane) ? (int)(v & 0x3fffffffu) : 0;
#pragma unroll
            for (int o = 16; o > 0; o >>= 1) val += __shfl_down_sync(0xffffffffu, val, o);
            if (t == 0) excl += val;
            done = (pm != 0u) || (p - 31 < 0);
            p -= 32;
        }
        if (t == 0) atomicExch(&tiles[tile], (2u << 30) | (unsigned)(excl + cnt));
    }
    return excl;  // lane 0
}

// ---------------- L3: redundant select1 + single-pass node compaction + zero hist1 ----------------
__global__ void k_nodes(int N, int NK, float* __restrict__ out_pool) {
    __shared__ int sc[256];
    __shared__ int sf2[64];
    __shared__ int s_bin, s_rem;
    __shared__ unsigned char sf[1024];
    __shared__ int ssum[256];
    __shared__ int s_gb;
    int bid = blockIdx.x, t = threadIdx.x;
    int prefix = g_prefix, krem = g_krem;
    block_select(g_c2, g_hist2, krem, sc, sf2, &s_bin, &s_rem);
    unsigned int tb = ((unsigned)prefix << 16) | (unsigned)s_bin;

    int base = bid * 1024;
    for (int i = t; i < 1024; i += 256) {
        int n = base + i;
        sf[i] = (n < N) ? (unsigned char)(__float_as_uint(g_scores[n]) >= tb) : (unsigned char)0;
    }
    __syncthreads();
    int loc[4];
    int s = 0;
#pragma unroll
    for (int j = 0; j < 4; j++) { loc[j] = s; s += sf[t * 4 + j]; }
    ssum[t] = s;
    __syncthreads();
    for (int off = 1; off < 256; off <<= 1) {
        int u = (t >= off) ? ssum[t - off] : 0;
        __syncthreads();
        ssum[t] += u;
        __syncthreads();
    }
    int cnt = ssum[255];
    if (t < 32) {
        int excl = lookback_excl(g_ntile, bid, cnt, t);
        if (t == 0) s_gb = excl;
    }
    __syncthreads();
    int texcl = ssum[t] - s;
    int gb = s_gb;
#pragma unroll
    for (int j = 0; j < 4; j++) {
        int n = base + t * 4 + j;
        if (n >= N) continue;
        int m = -1;
        if (sf[t * 4 + j]) {
            int r = gb + texcl + loc[j];
            if (r < NK) {  // stable truncation: first NK masked nodes by index
                m = r;
                g_poolidx[r] = n;
                out_pool[r] = (float)n;
            }
        }
        g_map[n] = m;
    }
    // zero hist1/c1 for next replay (last read was L2's select0)
    int G = gridDim.x * 256, gt = bid * 256 + t;
    for (int i = gt; i < 65536; i += G) g_hist1[i] = 0u;
    if (gt < 256) g_c1[gt] = 0u;
}

// ---------------- L4: staged edge compaction + zero hist2 ----------------
__global__ void k_edges(const int* __restrict__ ei, int E, int Ek,
                        float* __restrict__ out_ei, float* __restrict__ out_eo,
                        float* __restrict__ out_pe) {
    __shared__ int s_src[4096];
    __shared__ int s_dst[4096];
    __shared__ unsigned char sf[4096];
    __shared__ int ssum[256];
    __shared__ int s_gb;
    int bid = blockIdx.x, t = threadIdx.x;
    // zero hist2/c2 for next replay (last read was L3's select1)
    {
        int G = gridDim.x * 256, gt = bid * 256 + t;
        for (int i = gt; i < 65536; i += G) g_hist2[i] = 0u;
        if (gt < 256) g_c2[gt] = 0u;
    }
    int base = bid * 4096;
    for (int i = t; i < 4096; i += 256) {
        int e = base + i;
        unsigned char f = 0;
        if (e < E) {
            int sN = ei[e], dN = ei[E + e];
            s_src[i] = sN; s_dst[i] = dN;
            f = (unsigned char)((g_map[sN] >= 0 && g_map[dN] >= 0) ? 1 : 0);
            out_pe[e] = f ? 1.0f : 0.0f;
        }
        sf[i] = f;
    }
    __syncthreads();
    int loc[16];
    int s = 0;
#pragma unroll
    for (int j = 0; j < 16; j++) { loc[j] = s; s += sf[t * 16 + j]; }
    ssum[t] = s;
    __syncthreads();
    for (int off = 1; off < 256; off <<= 1) {
        int u = (t >= off) ? ssum[t - off] : 0;
        __syncthreads();
        ssum[t] += u;
        __syncthreads();
    }
    int cnt = ssum[255];
    if (t < 32) {
        int excl = lookback_excl(g_etile, bid, cnt, t);
        if (t == 0) s_gb = excl;
    }
    __syncthreads();
    int texcl = ssum[t] - s;
    int gb = s_gb;
    for (int j = 0; j < 16; j++) {
        int i = t * 16 + j;
        int e = base + i;
        if (e < E && sf[i]) {
            int r = gb + texcl + loc[j];
            int sN = s_src[i], dN = s_dst[i];
            out_ei[r]      = (float)sN;
            out_ei[Ek + r] = (float)dN;
            out_eo[r]      = (float)g_map[sN];
            out_eo[Ek + r] = (float)g_map[dN];
            g_kept[r] = e;
        }
    }
}

// ---------------- L5: pure gathers (edge_attr rows + new_x rows) ----------------
__global__ void k_gather(const float* __restrict__ ea, const float* __restrict__ x,
                         int Ek, int NK,
                         float* __restrict__ out_ea, float* __restrict__ out_x) {
    long long tid = (long long)blockIdx.x * blockDim.x + threadIdx.x;
    long long na = (long long)Ek * 8;     // attr float4s
    if (tid < na) {
        int r = (int)(tid >> 3), c = (int)(tid & 7);
        int e = g_kept[r];
        ((float4*)out_ea)[tid] = ((const float4*)ea)[(size_t)e * 8 + c];
    } else {
        long long t2 = tid - na;
        if (t2 < (long long)NK * 32) {
            int r = (int)(t2 >> 5), c = (int)(t2 & 31);
            int n = g_poolidx[r];
            ((float4*)out_x)[t2] = ((const float4*)x)[(size_t)n * 32 + c];
        }
    }
}

extern "C" void kernel_launch(void* const* d_in, const int* in_sizes, int n_in,
                              void* d_out, int out_size) {
    const float* x  = (const float*)d_in[0];   // (1, N, 128)
    const float* ea = (const float*)d_in[1];   // (1, E, 32)
    const float* w  = (const float*)d_in[2];   // (1, 128)
    const float* b  = (const float*)d_in[3];   // (1,)
    const int*   ei = (const int*)d_in[4];     // (2, E)

    int N  = in_sizes[0] / 128;
    int E  = in_sizes[4] / 2;
    int NK = N / 2;
    long long Ek_ll = ((long long)out_size - (long long)NK * 129 - (long long)E) / 36;
    int Ek = (int)Ek_ll;

    float* out    = (float*)d_out;
    float* out_x  = out;
    float* out_ei = out_x + (size_t)NK * 128;
    float* out_eo = out_ei + 2 * (size_t)Ek;
    float* out_ea = out_eo + 2 * (size_t)Ek;
    float* out_pi = out_ea + 32 * (size_t)Ek;
    float* out_pe = out_pi + (size_t)NK;

    // L1: scores + phase-0 histogram + tile-state zeroing
    k_scores<<<(N * 32 + 255) / 256, 256>>>(x, w, b, N);

    // L2: redundant select0 + phase-1 histogram
    k_phase1<<<(N + 255) / 256, 256>>>(N, NK);

    // L3: redundant select1 + node compaction (+ zero hist1/c1)
    int nbn = (N + 1023) / 1024;
    k_nodes<<<nbn, 256>>>(N, NK, out_pi);

    // L4: staged edge compaction (+ zero hist2/c2)
    int nbe = (E + 4095) / 4096;
    k_edges<<<nbe, 256>>>(ei, E, Ek, out_ei, out_eo, out_pe);

    // L5: fused pure gathers
    long long tot = (long long)Ek * 8 + (long long)NK * 32;
    k_gather<<<(int)((tot + 255) / 256), 256>>>(ea, x, Ek, NK, out_ea, out_x);
}

// round 15
// speedup vs baseline: 1.1887x; 1.0774x over previous
#include <cuda_runtime.h>

// Graph TopK pooling — R13: R11 skeleton, k_edges rewritten as register-resident
// ballot/popc compaction (smem 38KB -> ~0.1KB, 2 barriers instead of ~18).
//  L1 k_scores : scores + hi16/hi8 histogram + zero tile-states
//  L2 k_phase1 : redundant select0 (98 blocks) + lo16 histogram
//  L3 k_nodes  : redundant select1 + lookback node compaction; zero hist1/c1
//  L4 k_edges  : reg-resident edge compaction (512t, 8 edges/t); zero hist2/c2
//  L5 k_gather : pure gathers (edge_attr + new_x)

#define NMAX 100352
#define EMAX 1600000

__device__ float        g_scores[NMAX];
__device__ unsigned int g_hist1[65536];
__device__ unsigned int g_hist2[65536];
__device__ unsigned int g_c1[256];
__device__ unsigned int g_c2[256];
__device__ int          g_prefix;
__device__ int          g_krem;
__device__ int          g_map[NMAX];
__device__ int          g_poolidx[NMAX / 2 + 256];
__device__ int          g_kept[EMAX];
__device__ unsigned int g_ntile[256];   // packed flag<<30 | value
__device__ unsigned int g_etile[512];

// ---------------- redundant per-block radix select (~1.3 KB of L2 reads) ----------------
__device__ __forceinline__ void block_select(
    const unsigned int* __restrict__ C, const unsigned int* __restrict__ H,
    int k, int* sc, int* sf2, int* s_bin, int* s_rem)
{
    int t = threadIdx.x;
    int v = (t < 256) ? (int)C[t] : 0;
    if (t < 256) sc[t] = v;
    __syncthreads();
    for (int off = 1; off < 256; off <<= 1) {
        int u = (t >= off && t < 256) ? sc[t - off] : 0;
        __syncthreads();
        if (t < 256) sc[t] += u;
        __syncthreads();
    }
    if (t < 256) {
        int excl = sc[t] - v;
        if (k >= excl && k < excl + v) { *s_bin = t; *s_rem = k - excl; }
    }
    __syncthreads();
    int wb = *s_bin;
    int rem0 = *s_rem;
    __syncthreads();
    uint4 q = make_uint4(0, 0, 0, 0);
    int fv = 0;
    if (t < 64) {
        q = ((const uint4*)H)[wb * 64 + t];
        fv = (int)(q.x + q.y + q.z + q.w);
        sf2[t] = fv;
    }
    __syncthreads();
    for (int off = 1; off < 64; off <<= 1) {
        int u = (t >= off && t < 64) ? sf2[t - off] : 0;
        __syncthreads();
        if (t < 64) sf2[t] += u;
        __syncthreads();
    }
    if (t < 64) {
        int e2 = sf2[t] - fv;
        if (rem0 >= e2 && rem0 < e2 + fv) {
            int r = rem0 - e2;
            int bin;
            if (r < (int)q.x)                       { bin = wb * 256 + t * 4 + 0; }
            else { r -= (int)q.x; if (r < (int)q.y) { bin = wb * 256 + t * 4 + 1; }
            else { r -= (int)q.y; if (r < (int)q.z) { bin = wb * 256 + t * 4 + 2; }
            else { r -= (int)q.z;                     bin = wb * 256 + t * 4 + 3; } } }
            *s_bin = bin; *s_rem = r;
        }
    }
    __syncthreads();
}

// ---------------- L1: scores (warp/node) + phase-0 histogram + tile zeroing ----------------
__global__ void k_scores(const float* __restrict__ x, const float* __restrict__ w,
                         const float* __restrict__ b, int N) {
    int bidx = blockIdx.x, t = threadIdx.x;
    if (bidx == 0) {            // zero tile states consumed later this replay
        g_ntile[t] = 0u;
        g_etile[t] = 0u; g_etile[256 + t] = 0u;
    }
    int gtid = bidx * blockDim.x + t;
    int node = gtid >> 5, lane = gtid & 31;
    if (node >= N) return;
    float4 xv = ((const float4*)x)[node * 32 + lane];
    float4 wv = ((const float4*)w)[lane];
    float s = xv.x * wv.x + xv.y * wv.y + xv.z * wv.z + xv.w * wv.w;
#pragma unroll
    for (int o = 16; o > 0; o >>= 1) s += __shfl_down_sync(0xffffffffu, s, o);
    if (lane == 0) {
        float z = s + b[0];
        float sc;
        if (z >= 0.f) sc = 1.f / (1.f + expf(-z));
        else { float e = expf(z); sc = e / (1.f + e); }
        g_scores[node] = sc;
        unsigned int bits = __float_as_uint(sc);  // sc > 0: uint order == float order
        atomicAdd(&g_hist1[bits >> 16], 1u);      // hist1/c1 zeroed by prior replay L3
        atomicAdd(&g_c1[bits >> 24], 1u);
    }
}

// ---------------- L2: redundant select0 + phase-1 histogram (4 scores/thread) ----------------
__global__ void k_phase1(int N, int NK) {
    __shared__ int sc[256];
    __shared__ int sf2[64];
    __shared__ int s_bin, s_rem;
    int t = threadIdx.x;
    block_select(g_c1, g_hist1, NK - 1, sc, sf2, &s_bin, &s_rem);
    int prefix = s_bin;
    if (blockIdx.x == 0 && t == 0) { g_prefix = prefix; g_krem = s_rem; }
    int i = blockIdx.x * blockDim.x + t;
    int n4 = (N + 3) >> 2;
    if (i >= n4) return;
    float4 sv = ((const float4*)g_scores)[i];
    unsigned int bs[4] = { __float_as_uint(sv.x), __float_as_uint(sv.y),
                           __float_as_uint(sv.z), __float_as_uint(sv.w) };
#pragma unroll
    for (int j = 0; j < 4; j++) {
        int n = 4 * i + j;
        if (n >= N) break;
        unsigned int bits = bs[j];
        if ((int)(bits >> 16) == prefix) {
            atomicAdd(&g_hist2[bits & 0xffffu], 1u);  // hist2/c2 zeroed by prior replay L4
            atomicAdd(&g_c2[(bits >> 8) & 0xffu], 1u);
        }
    }
}

// ---------------- warp-parallel decoupled lookback (warp 0) ----------------
__device__ __forceinline__ int lookback_excl(unsigned int* tiles, int tile, int cnt, int t) {
    if (t == 0) {
        unsigned int word = (((tile == 0) ? 2u : 1u) << 30) | (unsigned)cnt;
        atomicExch(&tiles[tile], word);
    }
    __syncwarp();
    int excl = 0;
    if (tile > 0) {
        int p = tile - 1;
        bool done = false;
        while (!done) {
            int idx = p - t;
            unsigned int v = 0;
            if (idx >= 0) {
                v = *((volatile unsigned int*)&tiles[idx]);
                while ((v >> 30) == 0u) {
                    __nanosleep(40);
                    v = *((volatile unsigned int*)&tiles[idx]);
                }
            }
            unsigned int fl = (idx >= 0) ? (v >> 30) : 0u;
            unsigned int pm = __ballot_sync(0xffffffffu, fl == 2u);
            int stop_lane = (pm != 0u) ? (__ffs(pm) - 1) : 32;
            int val = (idx >= 0 && t <= stop_lane) ? (int)(v & 0x3fffffffu) : 0;
#pragma unroll
            for (int o = 16; o > 0; o >>= 1) val += __shfl_down_sync(0xffffffffu, val, o);
            if (t == 0) excl += val;
            done = (pm != 0u) || (p - 31 < 0);
            p -= 32;
        }
        if (t == 0) atomicExch(&tiles[tile], (2u << 30) | (unsigned)(excl + cnt));
    }
    return excl;  // lane 0
}

// ---------------- L3: redundant select1 + node compaction + zero hist1 ----------------
__global__ void k_nodes(int N, int NK, float* __restrict__ out_pool) {
    __shared__ int sc[256];
    __shared__ int sf2[64];
    __shared__ int s_bin, s_rem;
    __shared__ unsigned char sf[1024];
    __shared__ int ssum[256];
    __shared__ int s_gb;
    int bid = blockIdx.x, t = threadIdx.x;
    int prefix = g_prefix, krem = g_krem;
    block_select(g_c2, g_hist2, krem, sc, sf2, &s_bin, &s_rem);
    unsigned int tb = ((unsigned)prefix << 16) | (unsigned)s_bin;

    int base = bid * 1024;
    for (int i = t; i < 1024; i += 256) {
        int n = base + i;
        sf[i] = (n < N) ? (unsigned char)(__float_as_uint(g_scores[n]) >= tb) : (unsigned char)0;
    }
    __syncthreads();
    int loc[4];
    int s = 0;
#pragma unroll
    for (int j = 0; j < 4; j++) { loc[j] = s; s += sf[t * 4 + j]; }
    ssum[t] = s;
    __syncthreads();
    for (int off = 1; off < 256; off <<= 1) {
        int u = (t >= off) ? ssum[t - off] : 0;
        __syncthreads();
        ssum[t] += u;
        __syncthreads();
    }
    int cnt = ssum[255];
    if (t < 32) {
        int excl = lookback_excl(g_ntile, bid, cnt, t);
        if (t == 0) s_gb = excl;
    }
    __syncthreads();
    int texcl = ssum[t] - s;
    int gb = s_gb;
#pragma unroll
    for (int j = 0; j < 4; j++) {
        int n = base + t * 4 + j;
        if (n >= N) continue;
        int m = -1;
        if (sf[t * 4 + j]) {
            int r = gb + texcl + loc[j];
            if (r < NK) {  // stable truncation: first NK masked nodes by index
                m = r;
                g_poolidx[r] = n;
                out_pool[r] = (float)n;
            }
        }
        g_map[n] = m;
    }
    // zero hist1/c1 for next replay (last read was L2's select0)
    int G = gridDim.x * 256, gt = bid * 256 + t;
    for (int i = gt; i < 65536; i += G) g_hist1[i] = 0u;
    if (gt < 256) g_c1[gt] = 0u;
}

// ---------------- L4: register-resident edge compaction (512t, 8 edges/t) ----------------
__global__ void __launch_bounds__(512, 2)
k_edges(const int* __restrict__ ei, int E, int Ek,
        float* __restrict__ out_ei, float* __restrict__ out_eo,
        float* __restrict__ out_pe) {
    __shared__ int s_wsum[16];
    __shared__ int s_gb;
    int bid = blockIdx.x, t = threadIdx.x;
    int warp = t >> 5, lane = t & 31;
    // zero hist2/c2 for next replay (last read was L3's select1)
    {
        int G = gridDim.x * 512, gt = bid * 512 + t;
        for (int i = gt; i < 65536; i += G) g_hist2[i] = 0u;
        if (gt < 256) g_c2[gt] = 0u;
    }
    int e0 = bid * 4096 + t * 8;
    int sv[8], dv[8], ms[8], md[8];
    bool full = (e0 + 8 <= E);
    if (full) {
        const int4* ps = (const int4*)(ei + e0);
        int4 a = ps[0], c = ps[1];
        sv[0]=a.x; sv[1]=a.y; sv[2]=a.z; sv[3]=a.w;
        sv[4]=c.x; sv[5]=c.y; sv[6]=c.z; sv[7]=c.w;
        const int4* pd = (const int4*)(ei + E + e0);
        int4 d = pd[0], f = pd[1];
        dv[0]=d.x; dv[1]=d.y; dv[2]=d.z; dv[3]=d.w;
        dv[4]=f.x; dv[5]=f.y; dv[6]=f.z; dv[7]=f.w;
#pragma unroll
        for (int j = 0; j < 8; j++) { ms[j] = g_map[sv[j]]; md[j] = g_map[dv[j]]; }
    } else {
#pragma unroll
        for (int j = 0; j < 8; j++) {
            int e = e0 + j;
            if (e < E) { sv[j] = ei[e]; dv[j] = ei[E + e]; ms[j] = g_map[sv[j]]; md[j] = g_map[dv[j]]; }
            else       { sv[j] = 0; dv[j] = 0; ms[j] = -1; md[j] = -1; }
        }
    }
    unsigned int fm = 0u;
    float pe[8];
#pragma unroll
    for (int j = 0; j < 8; j++) {
        bool f = (ms[j] >= 0 && md[j] >= 0);
        fm |= (f ? 1u : 0u) << j;
        pe[j] = f ? 1.0f : 0.0f;
    }
    // out_pe: two coalesced float4 stores (or scalar on the ragged tail)
    if (full) {
        float4* po = (float4*)(out_pe + e0);
        po[0] = make_float4(pe[0], pe[1], pe[2], pe[3]);
        po[1] = make_float4(pe[4], pe[5], pe[6], pe[7]);
    } else {
#pragma unroll
        for (int j = 0; j < 8; j++) { int e = e0 + j; if (e < E) out_pe[e] = pe[j]; }
    }
    int cnt = __popc(fm);
    // warp inclusive scan of cnt
    int incl = cnt;
#pragma unroll
    for (int o = 1; o < 32; o <<= 1) {
        int v = __shfl_up_sync(0xffffffffu, incl, o);
        if (lane >= o) incl += v;
    }
    if (lane == 31) s_wsum[warp] = incl;
    __syncthreads();
    // warp 0: scan the 16 warp totals, lookback for global base
    if (t < 32) {
        int v = (t < 16) ? s_wsum[t] : 0;
        int wi = v;
#pragma unroll
        for (int o = 1; o < 16; o <<= 1) {
            int u = __shfl_up_sync(0xffffffffu, wi, o);
            if (lane >= o) wi += u;
        }
        if (t < 16) s_wsum[t] = wi - v;          // exclusive
        int total = __shfl_sync(0xffffffffu, wi, 15);
        int excl = lookback_excl(g_etile, bid, total, t);
        if (t == 0) s_gb = excl;
    }
    __syncthreads();
    int r = s_gb + s_wsum[warp] + (incl - cnt);
#pragma unroll
    for (int j = 0; j < 8; j++) {
        if (fm & (1u << j)) {
            out_ei[r]      = (float)sv[j];
            out_ei[Ek + r] = (float)dv[j];
            out_eo[r]      = (float)ms[j];
            out_eo[Ek + r] = (float)md[j];
            g_kept[r] = e0 + j;
            r++;
        }
    }
}

// ---------------- L5: pure gathers (edge_attr rows + new_x rows) ----------------
__global__ void k_gather(const float* __restrict__ ea, const float* __restrict__ x,
                         int Ek, int NK,
                         float* __restrict__ out_ea, float* __restrict__ out_x) {
    long long tid = (long long)blockIdx.x * blockDim.x + threadIdx.x;
    long long na = (long long)Ek * 8;     // attr float4s
    if (tid < na) {
        int r = (int)(tid >> 3), c = (int)(tid & 7);
        int e = g_kept[r];
        ((float4*)out_ea)[tid] = ((const float4*)ea)[(size_t)e * 8 + c];
    } else {
        long long t2 = tid - na;
        if (t2 < (long long)NK * 32) {
            int r = (int)(t2 >> 5), c = (int)(t2 & 31);
            int n = g_poolidx[r];
            ((float4*)out_x)[t2] = ((const float4*)x)[(size_t)n * 32 + c];
        }
    }
}

extern "C" void kernel_launch(void* const* d_in, const int* in_sizes, int n_in,
                              void* d_out, int out_size) {
    const float* x  = (const float*)d_in[0];   // (1, N, 128)
    const float* ea = (const float*)d_in[1];   // (1, E, 32)
    const float* w  = (const float*)d_in[2];   // (1, 128)
    const float* b  = (const float*)d_in[3];   // (1,)
    const int*   ei = (const int*)d_in[4];     // (2, E)

    int N  = in_sizes[0] / 128;
    int E  = in_sizes[4] / 2;
    int NK = N / 2;
    long long Ek_ll = ((long long)out_size - (long long)NK * 129 - (long long)E) / 36;
    int Ek = (int)Ek_ll;

    float* out    = (float*)d_out;
    float* out_x  = out;
    float* out_ei = out_x + (size_t)NK * 128;
    float* out_eo = out_ei + 2 * (size_t)Ek;
    float* out_ea = out_eo + 2 * (size_t)Ek;
    float* out_pi = out_ea + 32 * (size_t)Ek;
    float* out_pe = out_pi + (size_t)NK;

    // L1: scores + phase-0 histogram + tile-state zeroing
    k_scores<<<(N * 32 + 255) / 256, 256>>>(x, w, b, N);

    // L2: redundant select0 + phase-1 histogram (4 scores/thread)
    int nh = ((N + 3) / 4 + 255) / 256;
    k_phase1<<<nh, 256>>>(N, NK);

    // L3: redundant select1 + node compaction (+ zero hist1/c1)
    int nbn = (N + 1023) / 1024;
    k_nodes<<<nbn, 256>>>(N, NK, out_pi);

    // L4: register-resident edge compaction (+ zero hist2/c2)
    int nbe = (E + 4095) / 4096;
    k_edges<<<nbe, 512>>>(ei, E, Ek, out_ei, out_eo, out_pe);

    // L5: fused pure gathers
    long long tot = (long long)Ek * 8 + (long long)NK * 32;
    k_gather<<<(int)((tot + 255) / 256), 256>>>(ea, x, Ek, NK, out_ea, out_x);
}